// round 1
// baseline (speedup 1.0000x reference)
#include <cuda_runtime.h>
#include <cuda_bf16.h>

#define N_USERS 100000
#define N_ITEMS 50000
#define N_NODES (N_USERS + N_ITEMS)
#define D 64
#define F 768
#define N_EDGES 4800000
#define BATCH 4096
#define LN_EPS 1e-5f
#define N_LAYERS 3

// Scratch (device globals; no allocation allowed)
__device__ float g_emb[N_NODES * D];      // current embedding
__device__ float g_acc[N_NODES * D];      // running accumulator
__device__ float g_agg[N_NODES * D];      // segment-sum target
__device__ float g_ic [N_ITEMS * D];      // items_content (needed for loss)
__device__ float g_partials[4096];

// ---------------------------------------------------------------------------
// 1) emb/acc init for user rows
// ---------------------------------------------------------------------------
__global__ void init_users_kernel(const float* __restrict__ user_emb) {
    const int n = N_USERS * D / 4;
    const float4* u4 = (const float4*)user_emb;
    float4* e4 = (float4*)g_emb;
    float4* a4 = (float4*)g_acc;
    for (int i = blockIdx.x * blockDim.x + threadIdx.x; i < n;
         i += gridDim.x * blockDim.x) {
        float4 v = u4[i];
        e4[i] = v;
        a4[i] = v;
    }
}

// ---------------------------------------------------------------------------
// 2) Fused: items_content = cf @ W_proj + b_proj ; gate = sigmoid(cf @ w_gate + b_gate)
//    items = (1-gate)*item_emb + gate*items_content   -> g_emb/g_acc item rows
//    Tile: 64 items x 64 outputs, K-chunks of 32. 256 threads.
// ---------------------------------------------------------------------------
__global__ __launch_bounds__(256) void item_gemm_kernel(
    const float* __restrict__ cf, const float* __restrict__ Wp,
    const float* __restrict__ bp, const float* __restrict__ wg,
    const float* __restrict__ bg, const float* __restrict__ item_emb) {

    __shared__ float Cs[32][68];   // [k][item], padded; float4-aligned rows
    __shared__ float Ws[32][64];   // [k][d]
    __shared__ float wgs[32];
    __shared__ float gates[64];

    const int tid  = threadIdx.x;
    const int d    = tid & 63;     // output dim
    const int r    = tid >> 6;     // item group (0..3), 16 items each
    const int item0 = blockIdx.x * 64;

    float acc[16];
#pragma unroll
    for (int i = 0; i < 16; i++) acc[i] = 0.f;
    float gp = 0.f;

    for (int kt = 0; kt < F; kt += 32) {
        // load Cs transposed: [k][item]
#pragma unroll
        for (int j = 0; j < 8; j++) {
            int l = tid + j * 256;
            int it = l >> 5, k = l & 31;
            int item = item0 + it;
            Cs[k][it] = (item < N_ITEMS) ? cf[item * F + kt + k] : 0.f;
        }
        // load Ws: [k][d]
#pragma unroll
        for (int j = 0; j < 8; j++) {
            int l = tid + j * 256;
            int k = l >> 6, dd = l & 63;
            Ws[k][dd] = Wp[(kt + k) * D + dd];
        }
        if (tid < 32) wgs[tid] = wg[kt + tid];
        __syncthreads();

        // gate partial (64 threads, one item each)
        if (tid < 64) {
#pragma unroll
            for (int k = 0; k < 32; k++) gp += Cs[k][tid] * wgs[k];
        }
        // main MMA: FMA-bound (4x LDS.128 + 1 LDS.32 per 16 FMA)
#pragma unroll
        for (int k = 0; k < 32; k++) {
            float wv = Ws[k][d];
            const float4* cp = (const float4*)&Cs[k][r * 16];
#pragma unroll
            for (int q = 0; q < 4; q++) {
                float4 c = cp[q];
                acc[q * 4 + 0] += c.x * wv;
                acc[q * 4 + 1] += c.y * wv;
                acc[q * 4 + 2] += c.z * wv;
                acc[q * 4 + 3] += c.w * wv;
            }
        }
        __syncthreads();
    }

    if (tid < 64) gates[tid] = 1.f / (1.f + expf(-(gp + bg[0])));
    __syncthreads();

    const float bpd = bp[d];
#pragma unroll
    for (int it = 0; it < 16; it++) {
        int item = item0 + r * 16 + it;
        if (item < N_ITEMS) {
            float ic = acc[it] + bpd;
            g_ic[item * D + d] = ic;
            float g = gates[r * 16 + it];
            float e = (1.f - g) * item_emb[item * D + d] + g * ic;
            g_emb[(N_USERS + item) * D + d] = e;
            g_acc[(N_USERS + item) * D + d] = e;
        }
    }
}

// ---------------------------------------------------------------------------
// 3) zero agg
// ---------------------------------------------------------------------------
__global__ void zero_agg_kernel() {
    int i = blockIdx.x * blockDim.x + threadIdx.x;
    float4* p = (float4*)g_agg;
    if (i < N_NODES * D / 4) p[i] = make_float4(0.f, 0.f, 0.f, 0.f);
}

// ---------------------------------------------------------------------------
// 4) edge scatter: agg[dst] += w * emb[src]; 16 threads per edge, vector RED
// ---------------------------------------------------------------------------
__global__ __launch_bounds__(256) void scatter_kernel(
    const int* __restrict__ src, const int* __restrict__ dst,
    const float* __restrict__ w) {
    long long t = (long long)blockIdx.x * blockDim.x + threadIdx.x;
    int e = (int)(t >> 4);
    int lane = (int)(t & 15);
    if (e >= N_EDGES) return;
    int s  = src[e];
    int dd = dst[e];
    float ww = w[e];
    float4 v = ((const float4*)g_emb)[s * 16 + lane];
    float* ap = g_agg + dd * 64 + lane * 4;
    asm volatile("red.global.add.v4.f32 [%0], {%1,%2,%3,%4};"
                 :: "l"(ap), "f"(v.x * ww), "f"(v.y * ww), "f"(v.z * ww), "f"(v.w * ww)
                 : "memory");
}

// ---------------------------------------------------------------------------
// 5) layernorm(agg) + residual; acc += new emb.  Warp per node.
// ---------------------------------------------------------------------------
__global__ __launch_bounds__(256) void ln_res_kernel() {
    int warp = threadIdx.x >> 5;
    int lane = threadIdx.x & 31;
    int node = blockIdx.x * 8 + warp;
    if (node >= N_NODES) return;
    const float* a = g_agg + node * 64;
    float x0 = a[lane], x1 = a[lane + 32];
    float s = x0 + x1;
#pragma unroll
    for (int o = 16; o; o >>= 1) s += __shfl_xor_sync(0xFFFFFFFFu, s, o);
    float m = s * (1.f / 64.f);
    float d0 = x0 - m, d1 = x1 - m;
    float v = d0 * d0 + d1 * d1;
#pragma unroll
    for (int o = 16; o; o >>= 1) v += __shfl_xor_sync(0xFFFFFFFFu, v, o);
    float rs = rsqrtf(v * (1.f / 64.f) + LN_EPS);
    float* e  = g_emb + node * 64;
    float* ac = g_acc + node * 64;
    float e0 = d0 * rs + e[lane];
    float e1 = d1 * rs + e[lane + 32];
    e[lane] = e0; e[lane + 32] = e1;
    ac[lane] += e0; ac[lane + 32] += e1;
}

// ---------------------------------------------------------------------------
// 6) output gathers: users/pos/neg * 0.25
// ---------------------------------------------------------------------------
__global__ void gather_out_kernel(const int* __restrict__ u,
                                  const int* __restrict__ p,
                                  const int* __restrict__ n,
                                  float* __restrict__ out) {
    int b = blockIdx.x;
    int d = threadIdx.x;
    int which = blockIdx.y;
    int idx;
    if (which == 0)      idx = u[b];
    else if (which == 1) idx = N_USERS + p[b];
    else                 idx = N_USERS + n[b];
    out[((long long)which * BATCH + b) * D + d] = g_acc[idx * D + d] * 0.25f;
}

// ---------------------------------------------------------------------------
// 7) content loss: mean((acc_items*0.25 - items_content)^2) * 0.1
//    Deterministic two-stage reduction (no atomics).
// ---------------------------------------------------------------------------
__global__ __launch_bounds__(256) void loss_partial_kernel() {
    __shared__ float sh[256];
    float s = 0.f;
    for (int i = blockIdx.x * 256 + threadIdx.x; i < N_ITEMS * D;
         i += 4096 * 256) {
        float diff = g_acc[N_USERS * D + i] * 0.25f - g_ic[i];
        s += diff * diff;
    }
    sh[threadIdx.x] = s;
    __syncthreads();
#pragma unroll
    for (int o = 128; o; o >>= 1) {
        if (threadIdx.x < o) sh[threadIdx.x] += sh[threadIdx.x + o];
        __syncthreads();
    }
    if (threadIdx.x == 0) g_partials[blockIdx.x] = sh[0];
}

__global__ __launch_bounds__(1024) void loss_final_kernel(float* __restrict__ out) {
    __shared__ float sh[1024];
    float s = 0.f;
    for (int i = threadIdx.x; i < 4096; i += 1024) s += g_partials[i];
    sh[threadIdx.x] = s;
    __syncthreads();
#pragma unroll
    for (int o = 512; o; o >>= 1) {
        if (threadIdx.x < o) sh[threadIdx.x] += sh[threadIdx.x + o];
        __syncthreads();
    }
    if (threadIdx.x == 0)
        out[3 * BATCH * D] = sh[0] * (0.1f / (float)(N_ITEMS * D));
}

// ---------------------------------------------------------------------------
// launch
// ---------------------------------------------------------------------------
extern "C" void kernel_launch(void* const* d_in, const int* in_sizes, int n_in,
                              void* d_out, int out_size) {
    const int*   users     = (const int*)  d_in[0];
    const int*   pos_items = (const int*)  d_in[1];
    const int*   neg_items = (const int*)  d_in[2];
    const int*   edge_src  = (const int*)  d_in[3];
    const int*   edge_dst  = (const int*)  d_in[4];
    const float* edge_w    = (const float*)d_in[5];
    const float* user_emb  = (const float*)d_in[6];
    const float* item_emb  = (const float*)d_in[7];
    const float* cf        = (const float*)d_in[8];
    const float* Wp        = (const float*)d_in[9];
    const float* bp        = (const float*)d_in[10];
    const float* wg        = (const float*)d_in[11];
    const float* bg        = (const float*)d_in[12];
    float* out = (float*)d_out;

    // init users + fused item GEMM/gate/mix
    init_users_kernel<<<2048, 256>>>(user_emb);
    item_gemm_kernel<<<(N_ITEMS + 63) / 64, 256>>>(cf, Wp, bp, wg, bg, item_emb);

    // 3 propagation layers
    const int zero_blocks = (N_NODES * D / 4 + 255) / 256;
    const long long sc_threads = (long long)N_EDGES * 16;
    const int sc_blocks = (int)((sc_threads + 255) / 256);
    const int ln_blocks = (N_NODES + 7) / 8;
    for (int l = 0; l < N_LAYERS; l++) {
        zero_agg_kernel<<<zero_blocks, 256>>>();
        scatter_kernel<<<sc_blocks, 256>>>(edge_src, edge_dst, edge_w);
        ln_res_kernel<<<ln_blocks, 256>>>();
    }

    // outputs
    dim3 g(BATCH, 3);
    gather_out_kernel<<<g, D>>>(users, pos_items, neg_items, out);
    loss_partial_kernel<<<4096, 256>>>();
    loss_final_kernel<<<1, 1024>>>(out);
}

// round 3
// speedup vs baseline: 1.7437x; 1.7437x over previous
#include <cuda_runtime.h>
#include <cuda_bf16.h>

#define N_USERS 100000
#define N_ITEMS 50000
#define N_NODES (N_USERS + N_ITEMS)
#define D 64
#define F 768
#define N_EDGES 4800000
#define BATCH 4096
#define LN_EPS 1e-5f

#define SCAN_CHUNK 1024
#define NSCAN ((N_NODES + SCAN_CHUNK - 1) / SCAN_CHUNK)   // 147

// ---- scratch (device globals; no runtime allocation allowed) ----
__device__ float g_e0[N_NODES * D];
__device__ float g_e1[N_NODES * D];
__device__ float g_e2[N_NODES * D];
__device__ float g_e3[N_NODES * D];
__device__ float g_ic[N_ITEMS * D];
__device__ int   g_deg[N_NODES];
__device__ int   g_off[N_NODES + 1];
__device__ int   g_cursor[N_NODES];
__device__ int   g_blksum[NSCAN];
__device__ int   g_blkoff[NSCAN];
__device__ int   g_csr_src[N_EDGES];
__device__ float g_csr_w[N_EDGES];
__device__ float g_partials[4096];

// ---------------------------------------------------------------------------
// init user rows of e0
// ---------------------------------------------------------------------------
__global__ void init_users_kernel(const float* __restrict__ user_emb) {
    const int n = N_USERS * D / 4;
    const float4* u4 = (const float4*)user_emb;
    float4* e4 = (float4*)g_e0;
    for (int i = blockIdx.x * blockDim.x + threadIdx.x; i < n;
         i += gridDim.x * blockDim.x)
        e4[i] = u4[i];
}

// ---------------------------------------------------------------------------
// fused item GEMM + gate + mix -> e0 item rows, g_ic
// ---------------------------------------------------------------------------
__global__ __launch_bounds__(256) void item_gemm_kernel(
    const float* __restrict__ cf, const float* __restrict__ Wp,
    const float* __restrict__ bp, const float* __restrict__ wg,
    const float* __restrict__ bg, const float* __restrict__ item_emb) {

    __shared__ float Cs[32][68];
    __shared__ float Ws[32][64];
    __shared__ float wgs[32];
    __shared__ float gates[64];

    const int tid  = threadIdx.x;
    const int d    = tid & 63;
    const int r    = tid >> 6;
    const int item0 = blockIdx.x * 64;

    float acc[16];
#pragma unroll
    for (int i = 0; i < 16; i++) acc[i] = 0.f;
    float gp = 0.f;

    for (int kt = 0; kt < F; kt += 32) {
#pragma unroll
        for (int j = 0; j < 8; j++) {
            int l = tid + j * 256;
            int it = l >> 5, k = l & 31;
            int item = item0 + it;
            Cs[k][it] = (item < N_ITEMS) ? cf[item * F + kt + k] : 0.f;
        }
#pragma unroll
        for (int j = 0; j < 8; j++) {
            int l = tid + j * 256;
            int k = l >> 6, dd = l & 63;
            Ws[k][dd] = Wp[(kt + k) * D + dd];
        }
        if (tid < 32) wgs[tid] = wg[kt + tid];
        __syncthreads();

        if (tid < 64) {
#pragma unroll
            for (int k = 0; k < 32; k++) gp += Cs[k][tid] * wgs[k];
        }
#pragma unroll
        for (int k = 0; k < 32; k++) {
            float wv = Ws[k][d];
            const float4* cp = (const float4*)&Cs[k][r * 16];
#pragma unroll
            for (int q = 0; q < 4; q++) {
                float4 c = cp[q];
                acc[q * 4 + 0] += c.x * wv;
                acc[q * 4 + 1] += c.y * wv;
                acc[q * 4 + 2] += c.z * wv;
                acc[q * 4 + 3] += c.w * wv;
            }
        }
        __syncthreads();
    }

    if (tid < 64) gates[tid] = 1.f / (1.f + expf(-(gp + bg[0])));
    __syncthreads();

    const float bpd = bp[d];
#pragma unroll
    for (int it = 0; it < 16; it++) {
        int item = item0 + r * 16 + it;
        if (item < N_ITEMS) {
            float ic = acc[it] + bpd;
            g_ic[item * D + d] = ic;
            float g = gates[r * 16 + it];
            g_e0[(N_USERS + item) * D + d] =
                (1.f - g) * item_emb[item * D + d] + g * ic;
        }
    }
}

// ---------------------------------------------------------------------------
// CSR build
// ---------------------------------------------------------------------------
__global__ void zero_deg_kernel() {
    int i = blockIdx.x * blockDim.x + threadIdx.x;
    if (i < N_NODES) g_deg[i] = 0;
}

__global__ void hist_kernel(const int* __restrict__ dst) {
    int e = blockIdx.x * blockDim.x + threadIdx.x;
    if (e < N_EDGES) atomicAdd(&g_deg[dst[e]], 1);
}

__global__ __launch_bounds__(1024) void scan_sum_kernel() {
    __shared__ int sh[1024];
    int gid = blockIdx.x * SCAN_CHUNK + threadIdx.x;
    sh[threadIdx.x] = (gid < N_NODES) ? g_deg[gid] : 0;
    __syncthreads();
#pragma unroll
    for (int o = 512; o; o >>= 1) {
        if (threadIdx.x < o) sh[threadIdx.x] += sh[threadIdx.x + o];
        __syncthreads();
    }
    if (threadIdx.x == 0) g_blksum[blockIdx.x] = sh[0];
}

__global__ void scan_top_kernel() {
    if (threadIdx.x == 0) {
        int run = 0;
        for (int i = 0; i < NSCAN; i++) {
            g_blkoff[i] = run;
            run += g_blksum[i];
        }
    }
}

__global__ __launch_bounds__(1024) void scan_blocks_kernel() {
    __shared__ int sh[2][1024];
    int gid = blockIdx.x * SCAN_CHUNK + threadIdx.x;
    int v = (gid < N_NODES) ? g_deg[gid] : 0;
    sh[0][threadIdx.x] = v;
    __syncthreads();
    int cur = 0;
#pragma unroll
    for (int o = 1; o < 1024; o <<= 1) {
        int y = sh[cur][threadIdx.x];
        if ((int)threadIdx.x >= o) y += sh[cur][threadIdx.x - o];
        sh[1 - cur][threadIdx.x] = y;
        __syncthreads();
        cur = 1 - cur;
    }
    int inc = sh[cur][threadIdx.x];
    int base = g_blkoff[blockIdx.x];
    if (gid < N_NODES) {
        int exc = base + inc - v;
        g_off[gid] = exc;
        g_cursor[gid] = exc;
        if (gid == N_NODES - 1) g_off[N_NODES] = base + inc;
    }
}

__global__ void fill_kernel(const int* __restrict__ src,
                            const int* __restrict__ dst,
                            const float* __restrict__ w) {
    int e = blockIdx.x * blockDim.x + threadIdx.x;
    if (e < N_EDGES) {
        int pos = atomicAdd(&g_cursor[dst[e]], 1);
        g_csr_src[pos] = src[e];
        g_csr_w[pos] = w[e];
    }
}

// ---------------------------------------------------------------------------
// fused layer: agg = sum w*ein[src]; eout = LN(agg) + ein
// warp per node. Buffers resolved IN DEVICE CODE (host cannot take the
// address of __device__ symbols — that was the R2 bug).
// ---------------------------------------------------------------------------
__global__ __launch_bounds__(256) void layer_kernel(int l) {
    const float2* ein;
    float2* eout;
    if (l == 0)      { ein = (const float2*)g_e0; eout = (float2*)g_e1; }
    else if (l == 1) { ein = (const float2*)g_e1; eout = (float2*)g_e2; }
    else             { ein = (const float2*)g_e2; eout = (float2*)g_e3; }

    int warp = threadIdx.x >> 5;
    int lane = threadIdx.x & 31;
    int node = blockIdx.x * 8 + warp;
    if (node >= N_NODES) return;
    int beg = g_off[node];
    int end = g_off[node + 1];

    float a0 = 0.f, a1 = 0.f;
    int i = beg;
    for (; i + 4 <= end; i += 4) {
        int   s0 = g_csr_src[i + 0]; float w0 = g_csr_w[i + 0];
        int   s1 = g_csr_src[i + 1]; float w1 = g_csr_w[i + 1];
        int   s2 = g_csr_src[i + 2]; float w2 = g_csr_w[i + 2];
        int   s3 = g_csr_src[i + 3]; float w3 = g_csr_w[i + 3];
        float2 x0 = ein[s0 * 32 + lane];
        float2 x1 = ein[s1 * 32 + lane];
        float2 x2 = ein[s2 * 32 + lane];
        float2 x3 = ein[s3 * 32 + lane];
        a0 += w0 * x0.x; a1 += w0 * x0.y;
        a0 += w1 * x1.x; a1 += w1 * x1.y;
        a0 += w2 * x2.x; a1 += w2 * x2.y;
        a0 += w3 * x3.x; a1 += w3 * x3.y;
    }
    for (; i < end; i++) {
        int s = g_csr_src[i];
        float w = g_csr_w[i];
        float2 x = ein[s * 32 + lane];
        a0 += w * x.x; a1 += w * x.y;
    }

    float s = a0 + a1;
#pragma unroll
    for (int o = 16; o; o >>= 1) s += __shfl_xor_sync(0xFFFFFFFFu, s, o);
    float m = s * (1.f / 64.f);
    float d0 = a0 - m, d1 = a1 - m;
    float v = d0 * d0 + d1 * d1;
#pragma unroll
    for (int o = 16; o; o >>= 1) v += __shfl_xor_sync(0xFFFFFFFFu, v, o);
    float rs = rsqrtf(v * (1.f / 64.f) + LN_EPS);

    float2 r = ein[node * 32 + lane];
    eout[node * 32 + lane] = make_float2(d0 * rs + r.x, d1 * rs + r.y);
}

// ---------------------------------------------------------------------------
// outputs
// ---------------------------------------------------------------------------
__global__ void gather_out_kernel(const int* __restrict__ u,
                                  const int* __restrict__ p,
                                  const int* __restrict__ n,
                                  float* __restrict__ out) {
    int b = blockIdx.x;
    int d = threadIdx.x;
    int which = blockIdx.y;
    int idx;
    if (which == 0)      idx = u[b];
    else if (which == 1) idx = N_USERS + p[b];
    else                 idx = N_USERS + n[b];
    long long o = (long long)idx * D + d;
    out[((long long)which * BATCH + b) * D + d] =
        (g_e0[o] + g_e1[o] + g_e2[o] + g_e3[o]) * 0.25f;
}

__global__ __launch_bounds__(256) void loss_partial_kernel() {
    __shared__ float sh[256];
    const long long base = (long long)N_USERS * D;
    float s = 0.f;
    for (int i = blockIdx.x * 256 + threadIdx.x; i < N_ITEMS * D;
         i += 4096 * 256) {
        float fi = (g_e0[base + i] + g_e1[base + i] + g_e2[base + i] +
                    g_e3[base + i]) * 0.25f;
        float diff = fi - g_ic[i];
        s += diff * diff;
    }
    sh[threadIdx.x] = s;
    __syncthreads();
#pragma unroll
    for (int o = 128; o; o >>= 1) {
        if (threadIdx.x < o) sh[threadIdx.x] += sh[threadIdx.x + o];
        __syncthreads();
    }
    if (threadIdx.x == 0) g_partials[blockIdx.x] = sh[0];
}

__global__ __launch_bounds__(1024) void loss_final_kernel(float* __restrict__ out) {
    __shared__ float sh[1024];
    float s = 0.f;
    for (int i = threadIdx.x; i < 4096; i += 1024) s += g_partials[i];
    sh[threadIdx.x] = s;
    __syncthreads();
#pragma unroll
    for (int o = 512; o; o >>= 1) {
        if (threadIdx.x < o) sh[threadIdx.x] += sh[threadIdx.x + o];
        __syncthreads();
    }
    if (threadIdx.x == 0)
        out[3 * BATCH * D] = sh[0] * (0.1f / (float)(N_ITEMS * D));
}

// ---------------------------------------------------------------------------
// launch
// ---------------------------------------------------------------------------
extern "C" void kernel_launch(void* const* d_in, const int* in_sizes, int n_in,
                              void* d_out, int out_size) {
    const int*   users     = (const int*)  d_in[0];
    const int*   pos_items = (const int*)  d_in[1];
    const int*   neg_items = (const int*)  d_in[2];
    const int*   edge_src  = (const int*)  d_in[3];
    const int*   edge_dst  = (const int*)  d_in[4];
    const float* edge_w    = (const float*)d_in[5];
    const float* user_emb  = (const float*)d_in[6];
    const float* item_emb  = (const float*)d_in[7];
    const float* cf        = (const float*)d_in[8];
    const float* Wp        = (const float*)d_in[9];
    const float* bp        = (const float*)d_in[10];
    const float* wg        = (const float*)d_in[11];
    const float* bg        = (const float*)d_in[12];
    float* out = (float*)d_out;

    // base embeddings
    init_users_kernel<<<1024, 256>>>(user_emb);
    item_gemm_kernel<<<(N_ITEMS + 63) / 64, 256>>>(cf, Wp, bp, wg, bg, item_emb);

    // CSR build (rebuilt every call; replay-safe)
    zero_deg_kernel<<<(N_NODES + 255) / 256, 256>>>();
    hist_kernel<<<(N_EDGES + 255) / 256, 256>>>(edge_dst);
    scan_sum_kernel<<<NSCAN, 1024>>>();
    scan_top_kernel<<<1, 32>>>();
    scan_blocks_kernel<<<NSCAN, 1024>>>();
    fill_kernel<<<(N_EDGES + 255) / 256, 256>>>(edge_src, edge_dst, edge_w);

    // 3 fused propagation layers
    const int ln_blocks = (N_NODES + 7) / 8;
    layer_kernel<<<ln_blocks, 256>>>(0);
    layer_kernel<<<ln_blocks, 256>>>(1);
    layer_kernel<<<ln_blocks, 256>>>(2);

    // outputs
    dim3 g(BATCH, 3);
    gather_out_kernel<<<g, D>>>(users, pos_items, neg_items, out);
    loss_partial_kernel<<<4096, 256>>>();
    loss_final_kernel<<<1, 1024>>>(out);
}